// round 15
// baseline (speedup 1.0000x reference)
#include <cuda_runtime.h>
#include <cuda_fp16.h>
#include <cstdint>
#include <cstddef>
#include <cstring>

#define N_NODES 50000
#define N_EDGES 500000
#define IN_C 512
#define HID_C 256
#define OUT_C 128

#define SCAN_B 1024
#define NB ((N_NODES + SCAN_B - 1) / SCAN_B)   // 49
#define NHALF 24960                             // split point (multiple of 128 and 2)

// ---------------- scratch (device globals; no allocation) ----------------
__device__ int    g_degi[N_NODES];
__device__ int    g_cnt[N_NODES];
__device__ int    g_off[N_NODES + 1];
__device__ int    g_bsum[NB];
__device__ int2   g_csr[N_EDGES];             // (src, weight-as-bits fp32)
__device__ float  g_dis[N_NODES];
__device__ float  g_selfn[N_NODES];
__device__ __half g_h1h [(size_t)N_NODES * HID_C];  // GEMM1 out (fp16)
__device__ __half g_hh  [(size_t)N_NODES * HID_C];  // relu-agg out (fp16)
__device__ __half g_gh  [(size_t)N_NODES * HID_C];  // second agg out (fp16)
__device__ __half g_w1Th [HID_C * IN_C];            // [n][k] fp16
__device__ __half g_wcatTh[(2 * OUT_C) * HID_C];    // [n][k] fp16, [w_mu | w_ls]

// ---------------- bit-cast helpers ----------------
__device__ __forceinline__ uint32_t h2_as_u32(__half2 h) {
    uint32_t u; memcpy(&u, &h, 4); return u;
}
__device__ __forceinline__ __half2 u32_as_h2(uint32_t u) {
    __half2 h; memcpy(&h, &u, 4); return h;
}

// ---------------- streams/events (created pre-capture) ----------------
struct Aux {
    cudaStream_t s2;
    cudaEvent_t ev_fork, ev_w1, ev_join, ev_a, ev_g2a;
    Aux() {
        cudaStreamCreateWithFlags(&s2, cudaStreamNonBlocking);
        cudaEventCreateWithFlags(&ev_fork, cudaEventDisableTiming);
        cudaEventCreateWithFlags(&ev_w1,   cudaEventDisableTiming);
        cudaEventCreateWithFlags(&ev_join, cudaEventDisableTiming);
        cudaEventCreateWithFlags(&ev_a,    cudaEventDisableTiming);
        cudaEventCreateWithFlags(&ev_g2a,  cudaEventDisableTiming);
    }
};
static Aux g_aux;

// ---------------- CSR build ----------------
__global__ void k_count(const int* __restrict__ dst) {
    int e = blockIdx.x * blockDim.x + threadIdx.x;
    if (e < N_EDGES) atomicAdd(&g_degi[dst[e]], 1);
}

__global__ void k_scan1() {
    __shared__ int sh[SCAN_B];
    int tid = threadIdx.x;
    int i = blockIdx.x * SCAN_B + tid;
    int v = (i < N_NODES) ? g_degi[i] : 0;
    if (i < N_NODES) {
        float degf = (float)v + 1.0f;
        g_dis[i]   = rsqrtf(degf);
        g_selfn[i] = 1.0f / degf;
    }
    sh[tid] = v;
    __syncthreads();
    for (int off = 1; off < SCAN_B; off <<= 1) {
        int t = (tid >= off) ? sh[tid - off] : 0;
        __syncthreads();
        sh[tid] += t;
        __syncthreads();
    }
    if (i < N_NODES) g_off[i + 1] = sh[tid];
    if (tid == SCAN_B - 1) g_bsum[blockIdx.x] = sh[tid];   // raw block totals
    if (blockIdx.x == 0 && tid == 0) g_off[0] = 0;
}

// merged scan2+scan3: each block computes its own exclusive prefix of g_bsum
__global__ void k_scan3() {
    __shared__ int prefix;
    int tid = threadIdx.x;
    if (tid < 32) {
        int b = (int)blockIdx.x;
        int s = 0;
        if (tid < NB && tid < b)           s += g_bsum[tid];
        if (tid + 32 < NB && tid + 32 < b) s += g_bsum[tid + 32];
        #pragma unroll
        for (int o = 16; o > 0; o >>= 1)
            s += __shfl_down_sync(0xffffffffu, s, o);
        if (tid == 0) prefix = s;
    }
    __syncthreads();
    int i = blockIdx.x * SCAN_B + tid;
    if (i < N_NODES) g_off[i + 1] += prefix;
}

__global__ void k_fill(const int* __restrict__ src, const int* __restrict__ dst) {
    int e = blockIdx.x * blockDim.x + threadIdx.x;
    if (e < N_EDGES) {
        int d = dst[e];
        int s = src[e];
        int p = atomicAdd(&g_cnt[d], 1);
        int idx = g_off[d] + p;
        g_csr[idx] = make_int2(s, __float_as_int(g_dis[s]));
    }
}

// ---------------- weight transposes [n][k] fp16 ----------------
__global__ void k_w1T(const float* __restrict__ w1) {
    int j = blockIdx.x * blockDim.x + threadIdx.x;    // over HID_C*IN_C/8
    if (j < HID_C * IN_C / 8) {
        int n  = j / (IN_C / 8);
        int k0 = (j % (IN_C / 8)) * 8;
        __half o[8];
        #pragma unroll
        for (int q = 0; q < 8; q++)
            o[q] = __float2half_rn(w1[(size_t)(k0 + q) * HID_C + n]);
        *(uint4*)&g_w1Th[(size_t)n * IN_C + k0] = *(uint4*)o;
    }
}

__global__ void k_wcatT(const float* __restrict__ w_mu, const float* __restrict__ w_ls) {
    int i = blockIdx.x * blockDim.x + threadIdx.x;    // over 256*256
    if (i < (2 * OUT_C) * HID_C) {
        int n = i / HID_C;
        int k = i % HID_C;
        float v = (n < OUT_C) ? w_mu[(size_t)k * OUT_C + n]
                              : w_ls[(size_t)k * OUT_C + (n - OUT_C)];
        g_wcatTh[i] = __float2half_rn(v);
    }
}

// ---------------- fp16 tensor-core GEMM: ldmatrix + pipelined loads ----------------
// BM=128 BN=128 BK=16(halves), 256 threads = 8 warps, warp tile 32x64 (2x8 m16n8k16)
// A_F32: A is fp32 in gmem, converted in-register before STS (fuses x->fp16).
#define BM 128
#define BN 128
#define BKH 16
#define SSH 24     // 48B row stride: 8-row ldmatrix addrs distinct mod 128B

__device__ __forceinline__ void cp16(uint32_t saddr, const void* g, int sz) {
    asm volatile("cp.async.ca.shared.global [%0], [%1], 16, %2;" :: "r"(saddr), "l"(g), "r"(sz));
}
__device__ __forceinline__ void cp_commit() { asm volatile("cp.async.commit_group;"); }
__device__ __forceinline__ void cp_wait0()  { asm volatile("cp.async.wait_group 0;"); }
__device__ __forceinline__ void cp_wait1()  { asm volatile("cp.async.wait_group 1;"); }

__device__ __forceinline__ void ldsm4(uint32_t& r0, uint32_t& r1, uint32_t& r2, uint32_t& r3,
                                      uint32_t addr) {
    asm volatile("ldmatrix.sync.aligned.m8n8.x4.shared.b16 {%0,%1,%2,%3}, [%4];"
                 : "=r"(r0), "=r"(r1), "=r"(r2), "=r"(r3) : "r"(addr));
}

template<bool A_F32, bool HALF_OUT>
__global__ __launch_bounds__(256)
void k_gemm_f16(const void* __restrict__ Aptr, const __half* __restrict__ BT,
                const float* __restrict__ bias0, const float* __restrict__ bias1,
                void* __restrict__ out0v, void* __restrict__ out1v,
                int M, int K, int splitOut, int rowBase)
{
    __shared__ __half As[3][BM][SSH];
    __shared__ __half Bs[3][BN][SSH];

    const __half* Ah = (const __half*)Aptr;
    const float*  Af = (const float*)Aptr;

    const int tid  = threadIdx.x;
    const int lane = tid & 31;
    const int wid  = tid >> 5;

    const int row0 = rowBase + blockIdx.y * BM;
    const int col0 = blockIdx.x * BN;

    const int wm0 = (wid & 3) * 32;
    const int wn0 = (wid >> 2) * 64;

    // ldmatrix lane-address decomposition (halves)
    const int lr  = lane & 7;
    const int sel = lane >> 3;                 // 0..3
    const int a_ro = ((sel & 1) << 3) + lr;
    const int a_co = (sel >> 1) << 3;
    const int b_ro = ((sel >> 1) << 3) + lr;
    const int b_co = (sel & 1) << 3;

    float acc[2][8][4];
    #pragma unroll
    for (int mi = 0; mi < 2; mi++)
        #pragma unroll
        for (int ni = 0; ni < 8; ni++)
            #pragma unroll
            for (int q = 0; q < 4; q++) acc[mi][ni][q] = 0.0f;

    // per-thread load coords: 1 16B fp16 chunk (= 8 halves) for A and B each
    const int t_r = tid >> 1;              // 0..127
    const int t_c = (tid & 1) * 8;         // 0 or 8 (element offset)
    const int a_row_clamped = (row0 + t_r < M) ? (row0 + t_r) : (M - 1);

    float4 ar0, ar1;                        // fp32 A staging (A_F32 path)
    auto ldgA = [&](int k0) {
        const float* p = &Af[(size_t)a_row_clamped * K + k0 + t_c];
        ar0 = *(const float4*)p;
        ar1 = *(const float4*)(p + 4);
    };
    auto stsA = [&](int s) {
        uint4 o;
        o.x = h2_as_u32(__floats2half2_rn(ar0.x, ar0.y));
        o.y = h2_as_u32(__floats2half2_rn(ar0.z, ar0.w));
        o.z = h2_as_u32(__floats2half2_rn(ar1.x, ar1.y));
        o.w = h2_as_u32(__floats2half2_rn(ar1.z, ar1.w));
        *(uint4*)&As[s][t_r][t_c] = o;
    };
    auto cpA16 = [&](int s, int k0) {
        cp16((uint32_t)__cvta_generic_to_shared(&As[s][t_r][t_c]),
             &Ah[(size_t)a_row_clamped * K + k0 + t_c], 16);
    };
    auto cpB = [&](int s, int k0) {
        cp16((uint32_t)__cvta_generic_to_shared(&Bs[s][t_r][t_c]),
             &BT[(size_t)(col0 + t_r) * K + k0 + t_c], 16);
    };

    const int nIter = K / BKH;

    // ---- prologue: tiles 0 and 1 ----
    if (A_F32) {
        ldgA(0);       stsA(0);
        if (nIter > 1) { ldgA(BKH); stsA(1); }
        cpB(0, 0); cp_commit();
        if (nIter > 1) { cpB(1, BKH); cp_commit(); }
    } else {
        cpA16(0, 0); cpB(0, 0); cp_commit();
        if (nIter > 1) { cpA16(1, BKH); cpB(1, BKH); cp_commit(); }
    }

    for (int it = 0; it < nIter; it++) {
        if (it + 1 < nIter) cp_wait1(); else cp_wait0();
        __syncthreads();

        // issue next-next A global loads early (latency hidden under mma)
        if (A_F32 && it + 2 < nIter) ldgA((it + 2) * BKH);

        const int buf = it % 3;
        uint32_t a[2][4];
        #pragma unroll
        for (int mi = 0; mi < 2; mi++) {
            uint32_t addr = (uint32_t)__cvta_generic_to_shared(
                &As[buf][wm0 + mi * 16 + a_ro][a_co]);
            ldsm4(a[mi][0], a[mi][1], a[mi][2], a[mi][3], addr);
        }
        #pragma unroll
        for (int np = 0; np < 4; np++) {
            uint32_t bb[4];
            uint32_t addr = (uint32_t)__cvta_generic_to_shared(
                &Bs[buf][wn0 + np * 16 + b_ro][b_co]);
            ldsm4(bb[0], bb[1], bb[2], bb[3], addr);
            #pragma unroll
            for (int par = 0; par < 2; par++) {
                int ni = np * 2 + par;
                uint32_t b0 = bb[par * 2 + 0];
                uint32_t b1 = bb[par * 2 + 1];
                #pragma unroll
                for (int mi = 0; mi < 2; mi++) {
                    asm volatile(
                        "mma.sync.aligned.m16n8k16.row.col.f32.f16.f16.f32 "
                        "{%0,%1,%2,%3}, {%4,%5,%6,%7}, {%8,%9}, {%0,%1,%2,%3};\n"
                        : "+f"(acc[mi][ni][0]), "+f"(acc[mi][ni][1]),
                          "+f"(acc[mi][ni][2]), "+f"(acc[mi][ni][3])
                        : "r"(a[mi][0]), "r"(a[mi][1]), "r"(a[mi][2]), "r"(a[mi][3]),
                          "r"(b0), "r"(b1));
                }
            }
        }

        if (it + 2 < nIter) {
            int nb = (it + 2) % 3;
            if (A_F32) {
                stsA(nb);
                cpB(nb, (it + 2) * BKH);
            } else {
                cpA16(nb, (it + 2) * BKH);
                cpB(nb, (it + 2) * BKH);
            }
            cp_commit();
        }
    }

    // ---- epilogue: bias + split store ----
    const int lrow = lane >> 2;
    const int lcol = lane & 3;
    #pragma unroll
    for (int mi = 0; mi < 2; mi++) {
        #pragma unroll
        for (int half = 0; half < 2; half++) {
            int r = row0 + wm0 + mi * 16 + lrow + half * 8;
            if (r >= M) continue;
            #pragma unroll
            for (int ni = 0; ni < 8; ni++) {
                int c = col0 + wn0 + ni * 8 + lcol * 2;
                float v0 = acc[mi][ni][half * 2 + 0];
                float v1 = acc[mi][ni][half * 2 + 1];
                if (c < splitOut) {
                    if (bias0) { v0 += bias0[c]; v1 += bias0[c + 1]; }
                    if (HALF_OUT) {
                        *(__half2*)((__half*)out0v + (size_t)r * splitOut + c) =
                            __floats2half2_rn(v0, v1);
                    } else {
                        *(float2*)((float*)out0v + (size_t)r * splitOut + c) = make_float2(v0, v1);
                    }
                } else {
                    int cc = c - splitOut;
                    if (bias1) { v0 += bias1[cc]; v1 += bias1[cc + 1]; }
                    if (HALF_OUT) {
                        *(__half2*)((__half*)out1v + (size_t)r * splitOut + cc) =
                            __floats2half2_rn(v0, v1);
                    } else {
                        *(float2*)((float*)out1v + (size_t)r * splitOut + cc) = make_float2(v0, v1);
                    }
                }
            }
        }
    }
}

// ---------------- CSR aggregation (fp16 in/out, fp32 accumulate) ----------------
// 64 threads = 2 warps, each warp owns one node; thread owns 8 features.
__global__ void k_aggregate(const __half* __restrict__ hin,
                            const float* __restrict__ bias,
                            __half* __restrict__ hout,
                            int do_relu, int n0, int n1)
{
    int n = n0 + blockIdx.x * 2 + (threadIdx.x >> 5);
    if (n >= n1) return;
    int t = threadIdx.x & 31;
    int fo = t * 8;

    float acc[8];
    #pragma unroll
    for (int j = 0; j < 8; j++) acc[j] = 0.0f;

    int beg = g_off[n], end = g_off[n + 1];

    auto accum = [&](int2 e) {
        float w = __int_as_float(e.y);
        uint4 v = *(const uint4*)&hin[(size_t)e.x * HID_C + fo];
        float2 f0 = __half22float2(u32_as_h2(v.x));
        float2 f1 = __half22float2(u32_as_h2(v.y));
        float2 f2 = __half22float2(u32_as_h2(v.z));
        float2 f3 = __half22float2(u32_as_h2(v.w));
        acc[0] = fmaf(w, f0.x, acc[0]); acc[1] = fmaf(w, f0.y, acc[1]);
        acc[2] = fmaf(w, f1.x, acc[2]); acc[3] = fmaf(w, f1.y, acc[3]);
        acc[4] = fmaf(w, f2.x, acc[4]); acc[5] = fmaf(w, f2.y, acc[5]);
        acc[6] = fmaf(w, f3.x, acc[6]); acc[7] = fmaf(w, f3.y, acc[7]);
    };

    int i = beg;
    for (; i + 4 <= end; i += 4) {
        int2 e0 = g_csr[i + 0];
        int2 e1 = g_csr[i + 1];
        int2 e2 = g_csr[i + 2];
        int2 e3 = g_csr[i + 3];
        accum(e0); accum(e1); accum(e2); accum(e3);
    }
    for (; i < end; i++) accum(g_csr[i]);

    float dn = g_dis[n];
    float sn = g_selfn[n];
    uint4 hv = *(const uint4*)&hin[(size_t)n * HID_C + fo];
    float2 s0 = __half22float2(u32_as_h2(hv.x));
    float2 s1 = __half22float2(u32_as_h2(hv.y));
    float2 s2 = __half22float2(u32_as_h2(hv.z));
    float2 s3 = __half22float2(u32_as_h2(hv.w));
    float sv[8] = {s0.x, s0.y, s1.x, s1.y, s2.x, s2.y, s3.x, s3.y};

    float r[8];
    #pragma unroll
    for (int j = 0; j < 8; j++) {
        float b = bias ? bias[fo + j] : 0.0f;
        r[j] = dn * acc[j] + sn * sv[j] + b;
        if (do_relu) r[j] = fmaxf(r[j], 0.0f);
    }
    uint4 o;
    o.x = h2_as_u32(__floats2half2_rn(r[0], r[1]));
    o.y = h2_as_u32(__floats2half2_rn(r[2], r[3]));
    o.z = h2_as_u32(__floats2half2_rn(r[4], r[5]));
    o.w = h2_as_u32(__floats2half2_rn(r[6], r[7]));
    *(uint4*)&hout[(size_t)n * HID_C + fo] = o;
}

// ---------------- launch ----------------
extern "C" void kernel_launch(void* const* d_in, const int* in_sizes, int n_in,
                              void* d_out, int out_size)
{
    const float* x    = (const float*)d_in[0];
    const int*   ei   = (const int*)  d_in[1];
    const float* w1   = (const float*)d_in[2];
    const float* b1   = (const float*)d_in[3];
    const float* w_mu = (const float*)d_in[4];
    const float* b_mu = (const float*)d_in[5];
    const float* w_ls = (const float*)d_in[6];
    const float* b_ls = (const float*)d_in[7];
    float* out = (float*)d_out;

    const int* src = ei;
    const int* dst = ei + N_EDGES;

    void *p_h1h, *p_hh, *p_gh, *p_w1Th, *p_wcatTh, *p_degi, *p_cnt;
    cudaGetSymbolAddress(&p_h1h,    g_h1h);
    cudaGetSymbolAddress(&p_hh,     g_hh);
    cudaGetSymbolAddress(&p_gh,     g_gh);
    cudaGetSymbolAddress(&p_w1Th,   g_w1Th);
    cudaGetSymbolAddress(&p_wcatTh, g_wcatTh);
    cudaGetSymbolAddress(&p_degi,   g_degi);
    cudaGetSymbolAddress(&p_cnt,    g_cnt);
    __half* h1h    = (__half*)p_h1h;
    __half* hh     = (__half*)p_hh;
    __half* gh     = (__half*)p_gh;
    __half* w1Th   = (__half*)p_w1Th;
    __half* wcatTh = (__half*)p_wcatTh;

    // fork: w1T first (GEMM1 dependency), then CSR build + wcatT on side stream
    cudaEventRecord(g_aux.ev_fork, 0);
    cudaStreamWaitEvent(g_aux.s2, g_aux.ev_fork, 0);

    k_w1T<<<(HID_C * IN_C / 8 + 255) / 256, 256, 0, g_aux.s2>>>(w1);
    cudaEventRecord(g_aux.ev_w1, g_aux.s2);

    cudaMemsetAsync(p_degi, 0, N_NODES * sizeof(int), g_aux.s2);
    cudaMemsetAsync(p_cnt,  0, N_NODES * sizeof(int), g_aux.s2);
    k_count<<<(N_EDGES + 255) / 256, 256, 0, g_aux.s2>>>(dst);
    k_scan1<<<NB, SCAN_B, 0, g_aux.s2>>>();
    k_scan3<<<NB, SCAN_B, 0, g_aux.s2>>>();
    k_fill <<<(N_EDGES + 255) / 256, 256, 0, g_aux.s2>>>(src, dst);
    k_wcatT<<<((2 * OUT_C) * HID_C + 255) / 256, 256, 0, g_aux.s2>>>(w_mu, w_ls);
    cudaEventRecord(g_aux.ev_join, g_aux.s2);

    // main stream: GEMM1 directly on fp32 x (in-kernel conversion), overlaps CSR build
    cudaStreamWaitEvent(0, g_aux.ev_w1, 0);
    {
        dim3 grid(HID_C / BN, (N_NODES + BM - 1) / BM);
        k_gemm_f16<true, true><<<grid, 256>>>(x, w1Th, nullptr, nullptr,
                                              h1h, h1h, N_NODES, IN_C, HID_C, 0);
    }

    // join before aggregation
    cudaStreamWaitEvent(0, g_aux.ev_join, 0);

    // h = relu(Â h1 + b1)   (fp16 out, all nodes)
    k_aggregate<<<(N_NODES + 1) / 2, 64>>>(h1h, b1, hh, 1, 0, N_NODES);

    // g = Â h  — split into halves to overlap with GEMM2
    k_aggregate<<<NHALF / 2, 64>>>(hh, nullptr, gh, 0, 0, NHALF);
    cudaEventRecord(g_aux.ev_a, 0);

    // second half of agg2 on main stream
    k_aggregate<<<(N_NODES - NHALF + 1) / 2, 64>>>(hh, nullptr, gh, 0, NHALF, N_NODES);

    // GEMM2 half A on side stream (rows [0, NHALF)), concurrent with agg2-half-B
    cudaStreamWaitEvent(g_aux.s2, g_aux.ev_a, 0);
    {
        dim3 grid((2 * OUT_C) / BN, NHALF / BM);
        k_gemm_f16<false, false><<<grid, 256, 0, g_aux.s2>>>(
            gh, wcatTh, b_mu, b_ls,
            out, out + (size_t)N_NODES * OUT_C, N_NODES, HID_C, OUT_C, 0);
    }
    cudaEventRecord(g_aux.ev_g2a, g_aux.s2);

    // GEMM2 half B on main stream (rows [NHALF, N_NODES))
    {
        dim3 grid((2 * OUT_C) / BN, (N_NODES - NHALF + BM - 1) / BM);
        k_gemm_f16<false, false><<<grid, 256>>>(
            gh, wcatTh, b_mu, b_ls,
            out, out + (size_t)N_NODES * OUT_C, N_NODES, HID_C, OUT_C, NHALF);
    }

    // join GEMM2-half-A back into stream 0
    cudaStreamWaitEvent(0, g_aux.ev_g2a, 0);
}

// round 16
// speedup vs baseline: 1.0101x; 1.0101x over previous
#include <cuda_runtime.h>
#include <cuda_fp16.h>
#include <cstdint>
#include <cstddef>
#include <cstring>

#define N_NODES 50000
#define N_EDGES 500000
#define IN_C 512
#define HID_C 256
#define OUT_C 128

#define SCAN_B 1024
#define NB ((N_NODES + SCAN_B - 1) / SCAN_B)   // 49

// ---------------- scratch (device globals; no allocation) ----------------
__device__ int    g_degi[N_NODES];
__device__ int    g_cnt[N_NODES];
__device__ int    g_off[N_NODES + 1];
__device__ int    g_bsum[NB];
__device__ int2   g_csr[N_EDGES];             // (src, weight-as-bits fp32)
__device__ float  g_dis[N_NODES];
__device__ float  g_selfn[N_NODES];
__device__ __half g_h1h [(size_t)N_NODES * HID_C];  // GEMM1 out (fp16)
__device__ __half g_hh  [(size_t)N_NODES * HID_C];  // relu-agg out (fp16)
__device__ __half g_gh  [(size_t)N_NODES * HID_C];  // second agg out (fp16)
__device__ __half g_w1Th [HID_C * IN_C];            // [n][k] fp16
__device__ __half g_wcatTh[(2 * OUT_C) * HID_C];    // [n][k] fp16, [w_mu | w_ls]

// ---------------- bit-cast helpers ----------------
__device__ __forceinline__ uint32_t h2_as_u32(__half2 h) {
    uint32_t u; memcpy(&u, &h, 4); return u;
}
__device__ __forceinline__ __half2 u32_as_h2(uint32_t u) {
    __half2 h; memcpy(&h, &u, 4); return h;
}

// ---------------- streams/events (created pre-capture) ----------------
struct Aux {
    cudaStream_t s2;
    cudaEvent_t ev_fork, ev_w1, ev_join;
    Aux() {
        cudaStreamCreateWithFlags(&s2, cudaStreamNonBlocking);
        cudaEventCreateWithFlags(&ev_fork, cudaEventDisableTiming);
        cudaEventCreateWithFlags(&ev_w1,   cudaEventDisableTiming);
        cudaEventCreateWithFlags(&ev_join, cudaEventDisableTiming);
    }
};
static Aux g_aux;

// ---------------- CSR build ----------------
__global__ void k_count(const int* __restrict__ dst) {
    int e = blockIdx.x * blockDim.x + threadIdx.x;
    if (e < N_EDGES) atomicAdd(&g_degi[dst[e]], 1);
}

__global__ void k_scan1() {
    __shared__ int sh[SCAN_B];
    int tid = threadIdx.x;
    int i = blockIdx.x * SCAN_B + tid;
    int v = (i < N_NODES) ? g_degi[i] : 0;
    if (i < N_NODES) {
        float degf = (float)v + 1.0f;
        g_dis[i]   = rsqrtf(degf);
        g_selfn[i] = 1.0f / degf;
    }
    sh[tid] = v;
    __syncthreads();
    for (int off = 1; off < SCAN_B; off <<= 1) {
        int t = (tid >= off) ? sh[tid - off] : 0;
        __syncthreads();
        sh[tid] += t;
        __syncthreads();
    }
    if (i < N_NODES) g_off[i + 1] = sh[tid];
    if (tid == SCAN_B - 1) g_bsum[blockIdx.x] = sh[tid];   // raw block totals
    if (blockIdx.x == 0 && tid == 0) g_off[0] = 0;
}

// merged scan2+scan3: each block computes its own exclusive prefix of g_bsum
__global__ void k_scan3() {
    __shared__ int prefix;
    int tid = threadIdx.x;
    if (tid < 32) {
        int b = (int)blockIdx.x;
        int s = 0;
        if (tid < NB && tid < b)           s += g_bsum[tid];
        if (tid + 32 < NB && tid + 32 < b) s += g_bsum[tid + 32];
        #pragma unroll
        for (int o = 16; o > 0; o >>= 1)
            s += __shfl_down_sync(0xffffffffu, s, o);
        if (tid == 0) prefix = s;
    }
    __syncthreads();
    int i = blockIdx.x * SCAN_B + tid;
    if (i < N_NODES) g_off[i + 1] += prefix;
}

__global__ void k_fill(const int* __restrict__ src, const int* __restrict__ dst) {
    int e = blockIdx.x * blockDim.x + threadIdx.x;
    if (e < N_EDGES) {
        int d = dst[e];
        int s = src[e];
        int p = atomicAdd(&g_cnt[d], 1);
        int idx = g_off[d] + p;
        g_csr[idx] = make_int2(s, __float_as_int(g_dis[s]));
    }
}

// ---------------- weight transposes [n][k] fp16 ----------------
__global__ void k_w1T(const float* __restrict__ w1) {
    int j = blockIdx.x * blockDim.x + threadIdx.x;    // over HID_C*IN_C/8
    if (j < HID_C * IN_C / 8) {
        int n  = j / (IN_C / 8);
        int k0 = (j % (IN_C / 8)) * 8;
        __half o[8];
        #pragma unroll
        for (int q = 0; q < 8; q++)
            o[q] = __float2half_rn(w1[(size_t)(k0 + q) * HID_C + n]);
        *(uint4*)&g_w1Th[(size_t)n * IN_C + k0] = *(uint4*)o;
    }
}

__global__ void k_wcatT(const float* __restrict__ w_mu, const float* __restrict__ w_ls) {
    int i = blockIdx.x * blockDim.x + threadIdx.x;    // over 256*256
    if (i < (2 * OUT_C) * HID_C) {
        int n = i / HID_C;
        int k = i % HID_C;
        float v = (n < OUT_C) ? w_mu[(size_t)k * OUT_C + n]
                              : w_ls[(size_t)k * OUT_C + (n - OUT_C)];
        g_wcatTh[i] = __float2half_rn(v);
    }
}

// ---------------- fp16 tensor-core GEMM: ldmatrix + pipelined loads ----------------
// BM=128 BN=128 BK=16(halves), 256 threads = 8 warps, warp tile 32x64 (2x8 m16n8k16)
// A_F32: A is fp32 in gmem, converted in-register before STS (fuses x->fp16).
#define BM 128
#define BN 128
#define BKH 16
#define SSH 24     // 48B row stride: 8-row ldmatrix addrs distinct mod 128B

__device__ __forceinline__ void cp16(uint32_t saddr, const void* g, int sz) {
    asm volatile("cp.async.ca.shared.global [%0], [%1], 16, %2;" :: "r"(saddr), "l"(g), "r"(sz));
}
__device__ __forceinline__ void cp_commit() { asm volatile("cp.async.commit_group;"); }
__device__ __forceinline__ void cp_wait0()  { asm volatile("cp.async.wait_group 0;"); }
__device__ __forceinline__ void cp_wait1()  { asm volatile("cp.async.wait_group 1;"); }

__device__ __forceinline__ void ldsm4(uint32_t& r0, uint32_t& r1, uint32_t& r2, uint32_t& r3,
                                      uint32_t addr) {
    asm volatile("ldmatrix.sync.aligned.m8n8.x4.shared.b16 {%0,%1,%2,%3}, [%4];"
                 : "=r"(r0), "=r"(r1), "=r"(r2), "=r"(r3) : "r"(addr));
}

template<bool A_F32, bool HALF_OUT>
__global__ __launch_bounds__(256, 2)
void k_gemm_f16(const void* __restrict__ Aptr, const __half* __restrict__ BT,
                const float* __restrict__ bias0, const float* __restrict__ bias1,
                void* __restrict__ out0v, void* __restrict__ out1v,
                int M, int K, int splitOut)
{
    __shared__ __half As[3][BM][SSH];
    __shared__ __half Bs[3][BN][SSH];

    const __half* Ah = (const __half*)Aptr;
    const float*  Af = (const float*)Aptr;

    const int tid  = threadIdx.x;
    const int lane = tid & 31;
    const int wid  = tid >> 5;

    const int row0 = blockIdx.y * BM;
    const int col0 = blockIdx.x * BN;

    const int wm0 = (wid & 3) * 32;
    const int wn0 = (wid >> 2) * 64;

    // ldmatrix lane-address decomposition (halves)
    const int lr  = lane & 7;
    const int sel = lane >> 3;                 // 0..3
    const int a_ro = ((sel & 1) << 3) + lr;
    const int a_co = (sel >> 1) << 3;
    const int b_ro = ((sel >> 1) << 3) + lr;
    const int b_co = (sel & 1) << 3;

    float acc[2][8][4];
    #pragma unroll
    for (int mi = 0; mi < 2; mi++)
        #pragma unroll
        for (int ni = 0; ni < 8; ni++)
            #pragma unroll
            for (int q = 0; q < 4; q++) acc[mi][ni][q] = 0.0f;

    // per-thread load coords: 1 16B fp16 chunk (= 8 halves) for A and B each
    const int t_r = tid >> 1;              // 0..127
    const int t_c = (tid & 1) * 8;         // 0 or 8 (element offset)
    const int a_row_clamped = (row0 + t_r < M) ? (row0 + t_r) : (M - 1);

    float4 ar0, ar1;                        // fp32 A staging (A_F32 path)
    auto ldgA = [&](int k0) {
        const float* p = &Af[(size_t)a_row_clamped * K + k0 + t_c];
        ar0 = *(const float4*)p;
        ar1 = *(const float4*)(p + 4);
    };
    auto stsA = [&](int s) {
        uint4 o;
        o.x = h2_as_u32(__floats2half2_rn(ar0.x, ar0.y));
        o.y = h2_as_u32(__floats2half2_rn(ar0.z, ar0.w));
        o.z = h2_as_u32(__floats2half2_rn(ar1.x, ar1.y));
        o.w = h2_as_u32(__floats2half2_rn(ar1.z, ar1.w));
        *(uint4*)&As[s][t_r][t_c] = o;
    };
    auto cpA16 = [&](int s, int k0) {
        cp16((uint32_t)__cvta_generic_to_shared(&As[s][t_r][t_c]),
             &Ah[(size_t)a_row_clamped * K + k0 + t_c], 16);
    };
    auto cpB = [&](int s, int k0) {
        cp16((uint32_t)__cvta_generic_to_shared(&Bs[s][t_r][t_c]),
             &BT[(size_t)(col0 + t_r) * K + k0 + t_c], 16);
    };

    const int nIter = K / BKH;

    // ---- prologue: tiles 0 and 1 ----
    if (A_F32) {
        ldgA(0);       stsA(0);
        if (nIter > 1) { ldgA(BKH); stsA(1); }
        cpB(0, 0); cp_commit();
        if (nIter > 1) { cpB(1, BKH); cp_commit(); }
    } else {
        cpA16(0, 0); cpB(0, 0); cp_commit();
        if (nIter > 1) { cpA16(1, BKH); cpB(1, BKH); cp_commit(); }
    }

    for (int it = 0; it < nIter; it++) {
        if (it + 1 < nIter) cp_wait1(); else cp_wait0();
        __syncthreads();

        // issue next-next A global loads early (latency hidden under mma)
        if (A_F32 && it + 2 < nIter) ldgA((it + 2) * BKH);

        const int buf = it % 3;
        uint32_t a[2][4];
        #pragma unroll
        for (int mi = 0; mi < 2; mi++) {
            uint32_t addr = (uint32_t)__cvta_generic_to_shared(
                &As[buf][wm0 + mi * 16 + a_ro][a_co]);
            ldsm4(a[mi][0], a[mi][1], a[mi][2], a[mi][3], addr);
        }
        #pragma unroll
        for (int np = 0; np < 4; np++) {
            uint32_t bb[4];
            uint32_t addr = (uint32_t)__cvta_generic_to_shared(
                &Bs[buf][wn0 + np * 16 + b_ro][b_co]);
            ldsm4(bb[0], bb[1], bb[2], bb[3], addr);
            #pragma unroll
            for (int par = 0; par < 2; par++) {
                int ni = np * 2 + par;
                uint32_t b0 = bb[par * 2 + 0];
                uint32_t b1 = bb[par * 2 + 1];
                #pragma unroll
                for (int mi = 0; mi < 2; mi++) {
                    asm volatile(
                        "mma.sync.aligned.m16n8k16.row.col.f32.f16.f16.f32 "
                        "{%0,%1,%2,%3}, {%4,%5,%6,%7}, {%8,%9}, {%0,%1,%2,%3};\n"
                        : "+f"(acc[mi][ni][0]), "+f"(acc[mi][ni][1]),
                          "+f"(acc[mi][ni][2]), "+f"(acc[mi][ni][3])
                        : "r"(a[mi][0]), "r"(a[mi][1]), "r"(a[mi][2]), "r"(a[mi][3]),
                          "r"(b0), "r"(b1));
                }
            }
        }

        if (it + 2 < nIter) {
            int nb = (it + 2) % 3;
            if (A_F32) {
                stsA(nb);
                cpB(nb, (it + 2) * BKH);
            } else {
                cpA16(nb, (it + 2) * BKH);
                cpB(nb, (it + 2) * BKH);
            }
            cp_commit();
        }
    }

    // ---- epilogue: bias + split store ----
    const int lrow = lane >> 2;
    const int lcol = lane & 3;
    #pragma unroll
    for (int mi = 0; mi < 2; mi++) {
        #pragma unroll
        for (int half = 0; half < 2; half++) {
            int r = row0 + wm0 + mi * 16 + lrow + half * 8;
            if (r >= M) continue;
            #pragma unroll
            for (int ni = 0; ni < 8; ni++) {
                int c = col0 + wn0 + ni * 8 + lcol * 2;
                float v0 = acc[mi][ni][half * 2 + 0];
                float v1 = acc[mi][ni][half * 2 + 1];
                if (c < splitOut) {
                    if (bias0) { v0 += bias0[c]; v1 += bias0[c + 1]; }
                    if (HALF_OUT) {
                        *(__half2*)((__half*)out0v + (size_t)r * splitOut + c) =
                            __floats2half2_rn(v0, v1);
                    } else {
                        *(float2*)((float*)out0v + (size_t)r * splitOut + c) = make_float2(v0, v1);
                    }
                } else {
                    int cc = c - splitOut;
                    if (bias1) { v0 += bias1[cc]; v1 += bias1[cc + 1]; }
                    if (HALF_OUT) {
                        *(__half2*)((__half*)out1v + (size_t)r * splitOut + cc) =
                            __floats2half2_rn(v0, v1);
                    } else {
                        *(float2*)((float*)out1v + (size_t)r * splitOut + cc) = make_float2(v0, v1);
                    }
                }
            }
        }
    }
}

// ---------------- CSR aggregation (fp16 in/out, fp32 accumulate) ----------------
// 128 threads = 4 warps, each warp owns one node; thread owns 8 features.
__global__ void k_aggregate(const __half* __restrict__ hin,
                            const float* __restrict__ bias,
                            __half* __restrict__ hout,
                            int do_relu)
{
    int n = blockIdx.x * 4 + (threadIdx.x >> 5);
    if (n >= N_NODES) return;
    int t = threadIdx.x & 31;
    int fo = t * 8;

    float acc[8];
    #pragma unroll
    for (int j = 0; j < 8; j++) acc[j] = 0.0f;

    int beg = g_off[n], end = g_off[n + 1];

    auto accum = [&](int2 e) {
        float w = __int_as_float(e.y);
        uint4 v = *(const uint4*)&hin[(size_t)e.x * HID_C + fo];
        float2 f0 = __half22float2(u32_as_h2(v.x));
        float2 f1 = __half22float2(u32_as_h2(v.y));
        float2 f2 = __half22float2(u32_as_h2(v.z));
        float2 f3 = __half22float2(u32_as_h2(v.w));
        acc[0] = fmaf(w, f0.x, acc[0]); acc[1] = fmaf(w, f0.y, acc[1]);
        acc[2] = fmaf(w, f1.x, acc[2]); acc[3] = fmaf(w, f1.y, acc[3]);
        acc[4] = fmaf(w, f2.x, acc[4]); acc[5] = fmaf(w, f2.y, acc[5]);
        acc[6] = fmaf(w, f3.x, acc[6]); acc[7] = fmaf(w, f3.y, acc[7]);
    };

    int i = beg;
    for (; i + 4 <= end; i += 4) {
        int2 e0 = g_csr[i + 0];
        int2 e1 = g_csr[i + 1];
        int2 e2 = g_csr[i + 2];
        int2 e3 = g_csr[i + 3];
        accum(e0); accum(e1); accum(e2); accum(e3);
    }
    for (; i < end; i++) accum(g_csr[i]);

    float dn = g_dis[n];
    float sn = g_selfn[n];
    uint4 hv = *(const uint4*)&hin[(size_t)n * HID_C + fo];
    float2 s0 = __half22float2(u32_as_h2(hv.x));
    float2 s1 = __half22float2(u32_as_h2(hv.y));
    float2 s2 = __half22float2(u32_as_h2(hv.z));
    float2 s3 = __half22float2(u32_as_h2(hv.w));
    float sv[8] = {s0.x, s0.y, s1.x, s1.y, s2.x, s2.y, s3.x, s3.y};

    float r[8];
    #pragma unroll
    for (int j = 0; j < 8; j++) {
        float b = bias ? bias[fo + j] : 0.0f;
        r[j] = dn * acc[j] + sn * sv[j] + b;
        if (do_relu) r[j] = fmaxf(r[j], 0.0f);
    }
    uint4 o;
    o.x = h2_as_u32(__floats2half2_rn(r[0], r[1]));
    o.y = h2_as_u32(__floats2half2_rn(r[2], r[3]));
    o.z = h2_as_u32(__floats2half2_rn(r[4], r[5]));
    o.w = h2_as_u32(__floats2half2_rn(r[6], r[7]));
    *(uint4*)&hout[(size_t)n * HID_C + fo] = o;
}

// ---------------- launch ----------------
extern "C" void kernel_launch(void* const* d_in, const int* in_sizes, int n_in,
                              void* d_out, int out_size)
{
    const float* x    = (const float*)d_in[0];
    const int*   ei   = (const int*)  d_in[1];
    const float* w1   = (const float*)d_in[2];
    const float* b1   = (const float*)d_in[3];
    const float* w_mu = (const float*)d_in[4];
    const float* b_mu = (const float*)d_in[5];
    const float* w_ls = (const float*)d_in[6];
    const float* b_ls = (const float*)d_in[7];
    float* out = (float*)d_out;

    const int* src = ei;
    const int* dst = ei + N_EDGES;

    void *p_h1h, *p_hh, *p_gh, *p_w1Th, *p_wcatTh, *p_degi, *p_cnt;
    cudaGetSymbolAddress(&p_h1h,    g_h1h);
    cudaGetSymbolAddress(&p_hh,     g_hh);
    cudaGetSymbolAddress(&p_gh,     g_gh);
    cudaGetSymbolAddress(&p_w1Th,   g_w1Th);
    cudaGetSymbolAddress(&p_wcatTh, g_wcatTh);
    cudaGetSymbolAddress(&p_degi,   g_degi);
    cudaGetSymbolAddress(&p_cnt,    g_cnt);
    __half* h1h    = (__half*)p_h1h;
    __half* hh     = (__half*)p_hh;
    __half* gh     = (__half*)p_gh;
    __half* w1Th   = (__half*)p_w1Th;
    __half* wcatTh = (__half*)p_wcatTh;

    // fork: w1T first (GEMM1 dependency), then CSR build + wcatT on side stream
    cudaEventRecord(g_aux.ev_fork, 0);
    cudaStreamWaitEvent(g_aux.s2, g_aux.ev_fork, 0);

    k_w1T<<<(HID_C * IN_C / 8 + 255) / 256, 256, 0, g_aux.s2>>>(w1);
    cudaEventRecord(g_aux.ev_w1, g_aux.s2);

    cudaMemsetAsync(p_degi, 0, N_NODES * sizeof(int), g_aux.s2);
    cudaMemsetAsync(p_cnt,  0, N_NODES * sizeof(int), g_aux.s2);
    k_count<<<(N_EDGES + 255) / 256, 256, 0, g_aux.s2>>>(dst);
    k_scan1<<<NB, SCAN_B, 0, g_aux.s2>>>();
    k_scan3<<<NB, SCAN_B, 0, g_aux.s2>>>();
    k_fill <<<(N_EDGES + 255) / 256, 256, 0, g_aux.s2>>>(src, dst);
    k_wcatT<<<((2 * OUT_C) * HID_C + 255) / 256, 256, 0, g_aux.s2>>>(w_mu, w_ls);
    cudaEventRecord(g_aux.ev_join, g_aux.s2);

    // main stream: GEMM1 directly on fp32 x (in-kernel conversion), overlaps CSR build
    cudaStreamWaitEvent(0, g_aux.ev_w1, 0);
    {
        dim3 grid(HID_C / BN, (N_NODES + BM - 1) / BM);
        k_gemm_f16<true, true><<<grid, 256>>>(x, w1Th, nullptr, nullptr,
                                              h1h, h1h, N_NODES, IN_C, HID_C);
    }

    // join before aggregation
    cudaStreamWaitEvent(0, g_aux.ev_join, 0);

    // h = relu(Â h1 + b1)   (fp16 out)
    k_aggregate<<<(N_NODES + 3) / 4, 128>>>(h1h, b1, hh, 1);

    // g = Â h               (fp16 out, feeds GEMM2 A)
    k_aggregate<<<(N_NODES + 3) / 4, 128>>>(hh, nullptr, gh, 0);

    // [mu | logstd] = g @ wcat + [b_mu|b_ls]  (fp32 out, split halves)
    {
        dim3 grid((2 * OUT_C) / BN, (N_NODES + BM - 1) / BM);
        k_gemm_f16<false, false><<<grid, 256>>>(gh, wcatTh, b_mu, b_ls,
                                                out, out + (size_t)N_NODES * OUT_C,
                                                N_NODES, HID_C, OUT_C);
    }
}